// round 5
// baseline (speedup 1.0000x reference)
#include <cuda_runtime.h>
#include <mma.h>
using namespace nvcuda;

#define SEQ   4096
#define IND   1024
#define TD    3072   // 3 * 1024
#define DHEAD 1024

// Scratch (allocation-free rule: __device__ globals)
__device__ float g_qvk[SEQ * TD];   // [S, 3D]: cols [0,1024)=Q, [1024,2048)=V, [2048,3072)=K
__device__ float g_S[(size_t)SEQ * SEQ];  // scores, then probabilities in-place

constexpr int BM = 128, BN = 64, BK = 32;
constexpr int NTHREADS = 256;
constexpr int LDA_S = 40;   // BK + 8 pad (multiple of 8 for wmma ld)
constexpr int LDB_S = 72;   // BN + 8 pad

// ---------------- shared-tile loaders ----------------
__device__ __forceinline__ void load_tile_A(float* As, const float* A, int lda, int m0, int k0) {
    // As[BM][BK] stride LDA_S
    for (int s = threadIdx.x; s < BM * BK / 4; s += NTHREADS) {
        int row = s >> 3;            // 8 float4 per 32-wide row
        int col = (s & 7) * 4;
        float4 v = *reinterpret_cast<const float4*>(&A[(size_t)(m0 + row) * lda + k0 + col]);
        *reinterpret_cast<float4*>(&As[row * LDA_S + col]) = v;
    }
}
__device__ __forceinline__ void load_tile_B_nn(float* Bs, const float* B, int ldb, int k0, int n0) {
    // Bs[BK][BN] stride LDB_S; B is [K][N] row-major
    for (int s = threadIdx.x; s < BK * BN / 4; s += NTHREADS) {
        int row = s >> 4;            // 16 float4 per 64-wide row
        int col = (s & 15) * 4;
        float4 v = *reinterpret_cast<const float4*>(&B[(size_t)(k0 + row) * ldb + n0 + col]);
        *reinterpret_cast<float4*>(&Bs[row * LDB_S + col]) = v;
    }
}
__device__ __forceinline__ void load_tile_B_t(float* Bs, const float* B, int ldb, int k0, int n0) {
    // B is [N][K] row-major (the K tensor); want Bs[k][n] = B[n0+n][k0+k]
    for (int s = threadIdx.x; s < BK * BN / 4; s += NTHREADS) {
        int n  = s >> 3;             // 8 float4 along k per n-row
        int kc = (s & 7) * 4;
        float4 v = *reinterpret_cast<const float4*>(&B[(size_t)(n0 + n) * ldb + k0 + kc]);
        Bs[(kc + 0) * LDB_S + n] = v.x;
        Bs[(kc + 1) * LDB_S + n] = v.y;
        Bs[(kc + 2) * LDB_S + n] = v.z;
        Bs[(kc + 3) * LDB_S + n] = v.w;
    }
}

// ---------------- per-warp tf32 MMA on the staged tiles ----------------
__device__ __forceinline__ void warp_mma(
    const float* As, const float* Bs,
    wmma::fragment<wmma::accumulator, 16, 16, 8, float> (&c)[2][2],
    int warp_m, int warp_n)
{
#pragma unroll
    for (int kt = 0; kt < BK / 8; kt++) {
        wmma::fragment<wmma::matrix_a, 16, 16, 8, wmma::precision::tf32, wmma::row_major> a[2];
        wmma::fragment<wmma::matrix_b, 16, 16, 8, wmma::precision::tf32, wmma::row_major> b[2];
#pragma unroll
        for (int i = 0; i < 2; i++) {
            wmma::load_matrix_sync(a[i], &As[(warp_m * 32 + i * 16) * LDA_S + kt * 8], LDA_S);
#pragma unroll
            for (int t = 0; t < a[i].num_elements; t++)
                a[i].x[t] = wmma::__float_to_tf32(a[i].x[t]);
        }
#pragma unroll
        for (int j = 0; j < 2; j++) {
            wmma::load_matrix_sync(b[j], &Bs[(kt * 8) * LDB_S + warp_n * 32 + j * 16], LDB_S);
#pragma unroll
            for (int t = 0; t < b[j].num_elements; t++)
                b[j].x[t] = wmma::__float_to_tf32(b[j].x[t]);
        }
#pragma unroll
        for (int i = 0; i < 2; i++)
#pragma unroll
            for (int j = 0; j < 2; j++)
                wmma::mma_sync(c[i][j], a[i], b[j], c[i][j]);
    }
}

// ---------------- C = A @ B (row-major both), optional causal K truncation ----------------
__global__ __launch_bounds__(NTHREADS)
void gemm_nn_kernel(const float* __restrict__ A, int lda,
                    const float* __restrict__ B, int ldb,
                    float* __restrict__ C, int ldc,
                    int K, int causalK)
{
    __shared__ float As[BM * LDA_S];
    __shared__ float Bs[BK * LDB_S];
    const int m0 = blockIdx.y * BM;
    const int n0 = blockIdx.x * BN;
    const int Keff = causalK ? (blockIdx.y + 1) * BM : K;

    wmma::fragment<wmma::accumulator, 16, 16, 8, float> c[2][2];
#pragma unroll
    for (int i = 0; i < 2; i++)
#pragma unroll
        for (int j = 0; j < 2; j++)
            wmma::fill_fragment(c[i][j], 0.0f);

    const int warp = threadIdx.x >> 5;
    const int warp_m = warp >> 1, warp_n = warp & 1;

    for (int k0 = 0; k0 < Keff; k0 += BK) {
        load_tile_A(As, A, lda, m0, k0);
        load_tile_B_nn(Bs, B, ldb, k0, n0);
        __syncthreads();
        warp_mma(As, Bs, c, warp_m, warp_n);
        __syncthreads();
    }
#pragma unroll
    for (int i = 0; i < 2; i++)
#pragma unroll
        for (int j = 0; j < 2; j++)
            wmma::store_matrix_sync(
                &C[(size_t)(m0 + warp_m * 32 + i * 16) * ldc + n0 + warp_n * 32 + j * 16],
                c[i][j], ldc, wmma::mem_row_major);
}

// ---------------- S = Q @ K^T, only lower-triangular blocks ----------------
__global__ __launch_bounds__(NTHREADS)
void gemm_nt_causal_kernel(const float* __restrict__ Q, int lda,
                           const float* __restrict__ Kt, int ldb,
                           float* __restrict__ C, int ldc, int K)
{
    const int bi = blockIdx.y, bj = blockIdx.x;
    if (bj * BN >= (bi + 1) * BM) return;   // fully masked tile: skip

    __shared__ float As[BM * LDA_S];
    __shared__ float Bs[BK * LDB_S];
    const int m0 = bi * BM;
    const int n0 = bj * BN;

    wmma::fragment<wmma::accumulator, 16, 16, 8, float> c[2][2];
#pragma unroll
    for (int i = 0; i < 2; i++)
#pragma unroll
        for (int j = 0; j < 2; j++)
            wmma::fill_fragment(c[i][j], 0.0f);

    const int warp = threadIdx.x >> 5;
    const int warp_m = warp >> 1, warp_n = warp & 1;

    for (int k0 = 0; k0 < K; k0 += BK) {
        load_tile_A(As, Q, lda, m0, k0);
        load_tile_B_t(Bs, Kt, ldb, k0, n0);
        __syncthreads();
        warp_mma(As, Bs, c, warp_m, warp_n);
        __syncthreads();
    }
#pragma unroll
    for (int i = 0; i < 2; i++)
#pragma unroll
        for (int j = 0; j < 2; j++)
            wmma::store_matrix_sync(
                &C[(size_t)(m0 + warp_m * 32 + i * 16) * ldc + n0 + warp_n * 32 + j * 16],
                c[i][j], ldc, wmma::mem_row_major);
}

// ---------------- row softmax in-place on g_S; zero-fill to 128-block boundary ----------------
__global__ __launch_bounds__(256)
void softmax_kernel()
{
    const int i = blockIdx.x;
    float* row = g_S + (size_t)i * SEQ;
    const int n = i + 1;
    const float scale = 0.03125f;   // 1/sqrt(1024)
    __shared__ float red[256];

    float m = -1e30f;
    for (int j = threadIdx.x; j < n; j += 256) m = fmaxf(m, row[j] * scale);
    red[threadIdx.x] = m; __syncthreads();
    for (int s = 128; s > 0; s >>= 1) {
        if (threadIdx.x < s) red[threadIdx.x] = fmaxf(red[threadIdx.x], red[threadIdx.x + s]);
        __syncthreads();
    }
    m = red[0]; __syncthreads();

    float sum = 0.0f;
    for (int j = threadIdx.x; j < n; j += 256) sum += __expf(row[j] * scale - m);
    red[threadIdx.x] = sum; __syncthreads();
    for (int s = 128; s > 0; s >>= 1) {
        if (threadIdx.x < s) red[threadIdx.x] += red[threadIdx.x + s];
        __syncthreads();
    }
    sum = red[0];
    const float inv = 1.0f / sum;

    const int zend = ((i >> 7) + 1) << 7;   // end of this row's 128-row block, in cols
    for (int j = threadIdx.x; j < zend; j += 256)
        row[j] = (j < n) ? __expf(row[j] * scale - m) * inv : 0.0f;
}

extern "C" void kernel_launch(void* const* d_in, const int* in_sizes, int n_in,
                              void* d_out, int out_size)
{
    const float* x = (const float*)d_in[0];   // [4096, 1024]
    const float* W = (const float*)d_in[1];   // [1024, 3072]
    float* out = (float*)d_out;               // [4096, 1024]

    float* qvk; cudaGetSymbolAddress((void**)&qvk, g_qvk);
    float* S;   cudaGetSymbolAddress((void**)&S, g_S);

    // 1) qvk = x @ W
    {
        dim3 grid(TD / BN, SEQ / BM);
        gemm_nn_kernel<<<grid, NTHREADS>>>(x, IND, W, TD, qvk, TD, IND, 0);
    }
    // 2) S = Q @ K^T (raw; scale folded into softmax); lower-tri blocks only
    {
        dim3 grid(SEQ / BN, SEQ / BM);
        gemm_nt_causal_kernel<<<grid, NTHREADS>>>(qvk /*Q*/, TD, qvk + 2048 /*K*/, TD, S, SEQ, DHEAD);
    }
    // 3) softmax rows in-place (writes zeros for masked cols up to 128-block boundary)
    softmax_kernel<<<SEQ, 256>>>();
    // 4) out = P @ V with causal K truncation per row-block
    {
        dim3 grid(DHEAD / BN, SEQ / BM);
        gemm_nn_kernel<<<grid, NTHREADS>>>(S, SEQ, qvk + 1024 /*V*/, TD, out, DHEAD, SEQ, 1);
    }
}

// round 6
// speedup vs baseline: 1.1728x; 1.1728x over previous
#include <cuda_runtime.h>
#include <mma.h>
#include <cstdint>
using namespace nvcuda;

#define SEQ   4096
#define IND   1024
#define TD    3072   // 3 * 1024
#define DHEAD 1024

// Scratch (allocation-free rule: __device__ globals)
__device__ float g_qvk[SEQ * TD];        // [S,3D]: [0,1024)=Q, [1024,2048)=V, [2048,3072)=K
__device__ float g_S[(size_t)SEQ * SEQ]; // scores -> probabilities in-place

constexpr int BM = 128, BN = 128, BK = 32;
constexpr int NTHREADS = 256;
constexpr int LDA   = 36;    // padded stride for [x][32] tiles (A and transposed-B)
constexpr int LDBNN = 136;   // padded stride for [32][128] tiles (row-major B)
constexpr int STG   = 4608;  // floats per stage buffer (128*36 >= 32*136)
constexpr int SMEM_BYTES = 4 * STG * 4;  // 2 stages A + 2 stages B = 73728 B

// ---------------- cp.async helpers ----------------
__device__ __forceinline__ void cp16(void* dst, const void* src) {
    uint32_t d = (uint32_t)__cvta_generic_to_shared(dst);
    asm volatile("cp.async.cg.shared.global [%0], [%1], 16;\n" :: "r"(d), "l"(src));
}
__device__ __forceinline__ void cp_commit() {
    asm volatile("cp.async.commit_group;\n");
}

// ---------------- tile loaders (async) ----------------
// A tile: BM x BK  -> As[r*LDA + c]
// B tile (BT=false, row-major [K][N]): BK x BN -> Bs[k*LDBNN + n]
// B tile (BT=true,  B is [N][K] row-major): BN x BK -> Bs[n*LDA + k]  (col-major frag)
template<bool BT>
__device__ __forceinline__ void load_tiles(float* As, float* Bs,
    const float* A, int lda, const float* B, int ldb,
    int m0, int n0, int k0)
{
    const int tid = threadIdx.x;
#pragma unroll
    for (int t = 0; t < 4; t++) {
        int idx = tid + t * NTHREADS;
        int r = idx >> 3, c = (idx & 7) << 2;     // 8 float4 per 32-wide row
        cp16(&As[r * LDA + c], &A[(size_t)(m0 + r) * lda + k0 + c]);
    }
    if (BT) {
#pragma unroll
        for (int t = 0; t < 4; t++) {
            int idx = tid + t * NTHREADS;
            int r = idx >> 3, c = (idx & 7) << 2;
            cp16(&Bs[r * LDA + c], &B[(size_t)(n0 + r) * ldb + k0 + c]);
        }
    } else {
#pragma unroll
        for (int t = 0; t < 4; t++) {
            int idx = tid + t * NTHREADS;
            int r = idx >> 5, c = (idx & 31) << 2; // 32 float4 per 128-wide row
            cp16(&Bs[r * LDBNN + c], &B[(size_t)(k0 + r) * ldb + n0 + c]);
        }
    }
}

// ---------------- per-warp tf32 MMA on a staged tile ----------------
template<bool BT>
__device__ __forceinline__ void mma_stage(const float* As, const float* Bs,
    wmma::fragment<wmma::accumulator, 16, 16, 8, float> (&c)[2][4],
    int wm, int wn)
{
#pragma unroll
    for (int kt = 0; kt < BK / 8; kt++) {
        wmma::fragment<wmma::matrix_a, 16, 16, 8, wmma::precision::tf32, wmma::row_major> a[2];
#pragma unroll
        for (int i = 0; i < 2; i++) {
            wmma::load_matrix_sync(a[i], &As[(wm * 32 + i * 16) * LDA + kt * 8], LDA);
#pragma unroll
            for (int t = 0; t < a[i].num_elements; t++)
                a[i].x[t] = wmma::__float_to_tf32(a[i].x[t]);
        }
        if constexpr (BT) {
            wmma::fragment<wmma::matrix_b, 16, 16, 8, wmma::precision::tf32, wmma::col_major> b[4];
#pragma unroll
            for (int j = 0; j < 4; j++) {
                wmma::load_matrix_sync(b[j], &Bs[(wn * 64 + j * 16) * LDA + kt * 8], LDA);
#pragma unroll
                for (int t = 0; t < b[j].num_elements; t++)
                    b[j].x[t] = wmma::__float_to_tf32(b[j].x[t]);
            }
#pragma unroll
            for (int i = 0; i < 2; i++)
#pragma unroll
                for (int j = 0; j < 4; j++)
                    wmma::mma_sync(c[i][j], a[i], b[j], c[i][j]);
        } else {
            wmma::fragment<wmma::matrix_b, 16, 16, 8, wmma::precision::tf32, wmma::row_major> b[4];
#pragma unroll
            for (int j = 0; j < 4; j++) {
                wmma::load_matrix_sync(b[j], &Bs[(kt * 8) * LDBNN + wn * 64 + j * 16], LDBNN);
#pragma unroll
                for (int t = 0; t < b[j].num_elements; t++)
                    b[j].x[t] = wmma::__float_to_tf32(b[j].x[t]);
            }
#pragma unroll
            for (int i = 0; i < 2; i++)
#pragma unroll
                for (int j = 0; j < 4; j++)
                    wmma::mma_sync(c[i][j], a[i], b[j], c[i][j]);
        }
    }
}

// ---------------- pipelined 128x128x32 tf32 GEMM ----------------
// BT: B is [N][K] row-major (use col-major fragments)   -- for Q@K^T
// CSKIP: skip blocks fully above the diagonal           -- for Q@K^T
// CK: truncate K to (by+1)*BM                           -- for P@V
template<bool BT, bool CSKIP, bool CK>
__global__ void __launch_bounds__(NTHREADS, 1)
gemm_tf32(const float* __restrict__ A, int lda,
          const float* __restrict__ B, int ldb,
          float* __restrict__ C, int ldc, int K)
{
    const int bx = blockIdx.x, by = blockIdx.y;
    if (CSKIP && bx > by) return;

    extern __shared__ float smem[];
    float* As0 = smem;
    float* As1 = smem + STG;
    float* Bs0 = smem + 2 * STG;
    float* Bs1 = smem + 3 * STG;

    const int m0 = by * BM, n0 = bx * BN;
    const int Keff = CK ? (by + 1) * BM : K;
    const int NK = Keff / BK;

    wmma::fragment<wmma::accumulator, 16, 16, 8, float> c[2][4];
#pragma unroll
    for (int i = 0; i < 2; i++)
#pragma unroll
        for (int j = 0; j < 4; j++)
            wmma::fill_fragment(c[i][j], 0.0f);

    const int warp = threadIdx.x >> 5;
    const int wm = warp >> 1, wn = warp & 1;  // 4x2 warps, 32x64 per-warp tile

    load_tiles<BT>(As0, Bs0, A, lda, B, ldb, m0, n0, 0);
    cp_commit();

    for (int kb = 0; kb < NK; kb++) {
        if (kb + 1 < NK) {
            load_tiles<BT>((kb & 1) ? As0 : As1, (kb & 1) ? Bs0 : Bs1,
                           A, lda, B, ldb, m0, n0, (kb + 1) * BK);
            cp_commit();
            asm volatile("cp.async.wait_group 1;\n");
        } else {
            asm volatile("cp.async.wait_group 0;\n");
        }
        __syncthreads();
        mma_stage<BT>((kb & 1) ? As1 : As0, (kb & 1) ? Bs1 : Bs0, c, wm, wn);
        __syncthreads();
    }

#pragma unroll
    for (int i = 0; i < 2; i++)
#pragma unroll
        for (int j = 0; j < 4; j++)
            wmma::store_matrix_sync(
                &C[(size_t)(m0 + wm * 32 + i * 16) * ldc + n0 + wn * 64 + j * 16],
                c[i][j], ldc, wmma::mem_row_major);
}

// ---------------- row softmax in-place; zero-fill to 128-block boundary ----------------
__global__ void __launch_bounds__(256)
softmax_kernel()
{
    const int i = blockIdx.x;
    float* row = g_S + (size_t)i * SEQ;
    const int n = i + 1;
    const float scale = 0.03125f;   // 1/sqrt(1024)
    __shared__ float red[256];

    float m = -1e30f;
    for (int j = threadIdx.x; j < n; j += 256) m = fmaxf(m, row[j] * scale);
    red[threadIdx.x] = m; __syncthreads();
    for (int s = 128; s > 0; s >>= 1) {
        if (threadIdx.x < s) red[threadIdx.x] = fmaxf(red[threadIdx.x], red[threadIdx.x + s]);
        __syncthreads();
    }
    m = red[0]; __syncthreads();

    float sum = 0.0f;
    for (int j = threadIdx.x; j < n; j += 256) sum += __expf(row[j] * scale - m);
    red[threadIdx.x] = sum; __syncthreads();
    for (int s = 128; s > 0; s >>= 1) {
        if (threadIdx.x < s) red[threadIdx.x] += red[threadIdx.x + s];
        __syncthreads();
    }
    sum = red[0];
    const float inv = 1.0f / sum;

    const int zend = ((i >> 7) + 1) << 7;   // end of this row's 128-row block
    for (int j = threadIdx.x; j < zend; j += 256)
        row[j] = (j < n) ? __expf(row[j] * scale - m) * inv : 0.0f;
}

extern "C" void kernel_launch(void* const* d_in, const int* in_sizes, int n_in,
                              void* d_out, int out_size)
{
    const float* x = (const float*)d_in[0];   // [4096, 1024]
    const float* W = (const float*)d_in[1];   // [1024, 3072]
    float* out = (float*)d_out;               // [4096, 1024]

    float* qvk; cudaGetSymbolAddress((void**)&qvk, g_qvk);
    float* S;   cudaGetSymbolAddress((void**)&S, g_S);

    // Opt in to >48KB dynamic smem (idempotent; host-side, capture-safe)
    cudaFuncSetAttribute(gemm_tf32<false, false, false>,
                         cudaFuncAttributeMaxDynamicSharedMemorySize, SMEM_BYTES);
    cudaFuncSetAttribute(gemm_tf32<true, true, false>,
                         cudaFuncAttributeMaxDynamicSharedMemorySize, SMEM_BYTES);
    cudaFuncSetAttribute(gemm_tf32<false, false, true>,
                         cudaFuncAttributeMaxDynamicSharedMemorySize, SMEM_BYTES);

    // 1) qvk = x @ W            [4096,1024] @ [1024,3072]
    {
        dim3 grid(TD / BN, SEQ / BM);
        gemm_tf32<false, false, false><<<grid, NTHREADS, SMEM_BYTES>>>(
            x, IND, W, TD, qvk, TD, IND);
    }
    // 2) S = Q @ K^T (raw scores; scale folded into softmax), lower-tri blocks only
    {
        dim3 grid(SEQ / BN, SEQ / BM);
        gemm_tf32<true, true, false><<<grid, NTHREADS, SMEM_BYTES>>>(
            qvk /*Q*/, TD, qvk + 2048 /*K*/, TD, S, SEQ, DHEAD);
    }
    // 3) softmax rows in-place (zero-fills masked cols up to 128-block boundary)
    softmax_kernel<<<SEQ, 256>>>();
    // 4) out = P @ V with causal K truncation per row-block
    {
        dim3 grid(DHEAD / BN, SEQ / BM);
        gemm_tf32<false, false, true><<<grid, NTHREADS, SMEM_BYTES>>>(
            S, SEQ, qvk + 1024 /*V*/, TD, out, DHEAD, SEQ);
    }
}